// round 10
// baseline (speedup 1.0000x reference)
#include <cuda_runtime.h>
#include <cstdint>

#define SEQ    2048
#define BATCH  512
#define INPT   64
#define HIDDEN 128
#define KTOT   192             // combined [x ; h] reduction dim
#define KS     24              // per-thread k slice
#define NKS    8               // k slices
#define BB     4               // batches per block
#define NBLK   (BATCH / BB)    // 128 blocks -> 1 per SM
#define NTHR   512
#define RPAD   28              // region stride (24 data + 4 pad words)
#define BSTR   232             // per-batch stride (8*28 + 8), 232 % 32 = 8

// ---- packed f32x2 helpers (sm_103a) ----
__device__ __forceinline__ unsigned long long ffma2(unsigned long long a,
                                                    unsigned long long b,
                                                    unsigned long long c) {
    unsigned long long d;
    asm("fma.rn.f32x2 %0, %1, %2, %3;" : "=l"(d) : "l"(a), "l"(b), "l"(c));
    return d;
}
__device__ __forceinline__ unsigned long long pack2(float lo, float hi) {
    unsigned long long v;
    asm("mov.b64 %0, {%1, %2};" : "=l"(v) : "f"(lo), "f"(hi));
    return v;
}
__device__ __forceinline__ float lo_plus_hi(unsigned long long v) {
    float x, y;
    asm("mov.b64 {%0, %1}, %2;" : "=f"(x), "=f"(y) : "l"(v));
    return x + y;
}
__device__ __forceinline__ float tanh_fast(float z) {
    float az = fabsf(z);
    float e  = __expf(-2.0f * az);
    float r  = __fdividef(1.0f - e, 1.0f + e);
    return copysignf(r, z);
}
__device__ __forceinline__ void cp16(void* smem_dst, const float* gsrc) {
    unsigned dst = (unsigned)__cvta_generic_to_shared(smem_dst);
    asm volatile("cp.async.ca.shared.global [%0], [%1], 16;" :: "r"(dst), "l"(gsrc));
}

// combined weight element: c<64 -> W_ih[j][c], c>=64 -> W_hh[j][c-64]
__device__ __forceinline__ float wcomb(const float* W_ih, const float* W_hh,
                                       int j, int c) {
    return (c < INPT) ? W_ih[j * INPT + c] : W_hh[j * HIDDEN + (c - INPT)];
}
// smem word offset of combined index c within one batch region
__device__ __forceinline__ int cword(int c) {
    return (c / KS) * RPAD + (c % KS);
}

// ============================================================================
// Fused recurrence, 1 block/SM, 512 thr. u(t) = [x(t)(64); h(t)(128)], K=192.
// smem v[3][4][232] triple-buffered; combined idx c at word cword(c).
// Thread: lane = ks*4 + jl, jl = lane&3, ks = lane>>2 in [0,8);
//   jp = wid*4 + jl; owns rows jp, jp+64; k-slice [ks*24, ks*24+24);
//   ALL 4 batches. 24 LDS.128 (conflict-free) + 96 FMA2, 48 weight regs.
// Chunk i of a slice holds f32x2 pairs 2i, 2i+1 (4 floats).
// 2-stage load pipeline across batches hides LDS latency.
// ============================================================================
__global__ void __launch_bounds__(NTHR, 1)
rnn_fused_kernel(const float* __restrict__ xs,
                 const float* __restrict__ W_ih,
                 const float* __restrict__ W_hh,
                 const float* __restrict__ b_ih,
                 const float* __restrict__ b_hh,
                 const float* __restrict__ W_out,
                 const float* __restrict__ b_out,
                 float* __restrict__ out) {
    __shared__ __align__(16) float v[3][BB][BSTR];

    const int tid  = threadIdx.x;
    const int wid  = tid >> 5;
    const int lane = tid & 31;
    const int jp   = wid * 4 + (lane & 3);
    const int ks   = lane >> 2;            // [0,8)
    const long bbase = (long)blockIdx.x * BB;

    const int k0v = ks & 1;                // reduction selectors
    const int k1v = (ks >> 1) & 1;
    const int k2v = ks >> 2;

    // final-value slot: j_st = jp + 64*k1, b_st = 2*k0 + k2
    const int j_st = jp + 64 * k1v;
    const int b_st = 2 * k0v + k2v;
    const int st_off = b_st * BSTR + cword(INPT + j_st);

    // weights: rows jp, jp+64, k-slice [ks*24, ks*24+24) -> 12 pairs each
    unsigned long long w0[KS / 2], w1[KS / 2];
    #pragma unroll
    for (int i = 0; i < KS / 2; i++) {
        int ca = ks * KS + 2 * i;
        w0[i] = pack2(wcomb(W_ih, W_hh, jp,      ca),
                      wcomb(W_ih, W_hh, jp,      ca + 1));
        w1[i] = pack2(wcomb(W_ih, W_hh, jp + 64, ca),
                      wcomb(W_ih, W_hh, jp + 64, ca + 1));
    }
    const float bias = b_ih[j_st] + b_hh[j_st];

    // init: zero all buffers (h0 = 0); stage x(0)->buf0, x(1)->buf1
    for (int i = tid; i < 3 * BB * BSTR; i += NTHR)
        (&v[0][0][0])[i] = 0.0f;
    __syncthreads();
    if (tid < BB * 16) {
        int b = tid >> 4, seg = tid & 15;
        int wo = cword(seg * 4);
        cp16(&v[0][b][wo], xs + (bbase + b) * INPT + seg * 4);
        cp16(&v[1][b][wo], xs + ((long)BATCH + bbase + b) * INPT + seg * 4);
    }
    asm volatile("cp.async.commit_group;" ::);
    asm volatile("cp.async.wait_group 0;" ::);
    __syncthreads();

    const int kbase = ks * RPAD;   // word offset of this thread's k-slice

    auto step = [&](int p0, int p1, int p2, int t) {
        // prefetch x(t+2) into buffer p2 (readers finished last step)
        if (t + 2 < SEQ && tid < BB * 16) {
            int b = tid >> 4, seg = tid & 15;
            cp16(&v[p2][b][cword(seg * 4)],
                 xs + ((long)(t + 2) * BATCH + bbase + b) * INPT + seg * 4);
        }
        asm volatile("cp.async.commit_group;" ::);

        // 2-stage pipelined loads across batches; 6 chunks (24 floats) each.
        // Stage chunks 0..2; chunks 3..5 loaded directly inside the b-loop.
        const float* base = &v[p0][0][kbase];
        ulonglong2 st0[3], st1[3];
        const ulonglong2* hb0 = reinterpret_cast<const ulonglong2*>(base);
        #pragma unroll
        for (int i = 0; i < 3; i++) st0[i] = hb0[i];

        unsigned long long acc0[BB], acc1[BB];   // rows jp / jp+64 per batch
        #pragma unroll
        for (int b = 0; b < BB; b++) { acc0[b] = 0ull; acc1[b] = 0ull; }

        #pragma unroll
        for (int b = 0; b < BB; b++) {
            // prefetch next batch's chunks 0..2 into the other stage
            if (b + 1 < BB) {
                const ulonglong2* hn = reinterpret_cast<const ulonglong2*>(
                    base + (b + 1) * BSTR);
                if (b & 1) { st0[0]=hn[0]; st0[1]=hn[1]; st0[2]=hn[2]; }
                else       { st1[0]=hn[0]; st1[1]=hn[1]; st1[2]=hn[2]; }
            }
            const ulonglong2* s = (b & 1) ? st1 : st0;
            #pragma unroll
            for (int i = 0; i < 3; i++) {          // chunk i -> pairs 2i, 2i+1
                ulonglong2 q = s[i];
                acc0[b] = ffma2(w0[2 * i],     q.x, acc0[b]);
                acc1[b] = ffma2(w1[2 * i],     q.x, acc1[b]);
                acc0[b] = ffma2(w0[2 * i + 1], q.y, acc0[b]);
                acc1[b] = ffma2(w1[2 * i + 1], q.y, acc1[b]);
            }
            // chunks 3..5 -> pairs 6..11, loaded directly
            const ulonglong2* s2 = reinterpret_cast<const ulonglong2*>(
                base + b * BSTR) + 3;
            #pragma unroll
            for (int i = 0; i < 3; i++) {
                ulonglong2 q = s2[i];
                acc0[b] = ffma2(w0[6 + 2 * i],     q.x, acc0[b]);
                acc1[b] = ffma2(w1[6 + 2 * i],     q.x, acc1[b]);
                acc0[b] = ffma2(w0[6 + 2 * i + 1], q.y, acc0[b]);
                acc1[b] = ffma2(w1[6 + 2 * i + 1], q.y, acc1[b]);
            }
        }

        float p0r[BB], p1r[BB];
        #pragma unroll
        for (int b = 0; b < BB; b++) {
            p0r[b] = lo_plus_hi(acc0[b]);
            p1r[b] = lo_plus_hi(acc1[b]);
        }

        // Round 1 (xor 4, ks bit0): k0=0 keeps b{0,1}, k0=1 keeps b{2,3}
        float s00 = k0v ? p0r[0] : p0r[2];
        float s01 = k0v ? p0r[1] : p0r[3];
        float s10 = k0v ? p1r[0] : p1r[2];
        float s11 = k0v ? p1r[1] : p1r[3];
        float r00 = __shfl_xor_sync(0xffffffffu, s00, 4);
        float r01 = __shfl_xor_sync(0xffffffffu, s01, 4);
        float r10 = __shfl_xor_sync(0xffffffffu, s10, 4);
        float r11 = __shfl_xor_sync(0xffffffffu, s11, 4);
        float q00 = (k0v ? p0r[2] : p0r[0]) + r00;  // (row0, c=0)
        float q01 = (k0v ? p0r[3] : p0r[1]) + r01;  // (row0, c=1)
        float q10 = (k0v ? p1r[2] : p1r[0]) + r10;  // (row1, c=0)
        float q11 = (k0v ? p1r[3] : p1r[1]) + r11;  // (row1, c=1)

        // Round 2 (xor 8, ks bit1): k1=0 keeps row0, k1=1 keeps row1
        float sA = k1v ? q00 : q10;
        float sB = k1v ? q01 : q11;
        float rA = __shfl_xor_sync(0xffffffffu, sA, 8);
        float rB = __shfl_xor_sync(0xffffffffu, sB, 8);
        float u0 = (k1v ? q10 : q00) + rA;   // (j_st, c=0)
        float u1 = (k1v ? q11 : q01) + rB;   // (j_st, c=1)

        // Round 3 (xor 16, ks bit2): k2=0 keeps c=0, k2=1 keeps c=1
        float sC = k2v ? u0 : u1;
        float rC = __shfl_xor_sync(0xffffffffu, sC, 16);
        float z  = (k2v ? u1 : u0) + rC + bias;

        v[p1][0][st_off] = tanh_fast(z);     // batch folded into st_off

        asm volatile("cp.async.wait_group 1;" ::);  // x(t+1), committed last step
        __syncthreads();
    };

    // 2046 steps in rotations of 3, then 2 tail steps. Final h in buffer 2.
    for (int t = 0; t < SEQ - 2; t += 3) {
        step(0, 1, 2, t);
        step(1, 2, 0, t + 1);
        step(2, 0, 1, t + 2);
    }
    step(0, 1, 2, SEQ - 2);
    step(1, 2, 0, SEQ - 1);

    // output projection: out[b] = h_final[b] . W_out + b_out  (h in v[2])
    if (tid < BB * 32) {
        int b = tid >> 5, l = tid & 31;
        float sacc = 0.0f;
        #pragma unroll
        for (int m = 0; m < 4; m++) {
            int jj = l + 32 * m;
            sacc += v[2][b][cword(INPT + jj)] * W_out[jj];
        }
        #pragma unroll
        for (int off = 16; off; off >>= 1)
            sacc += __shfl_down_sync(0xffffffffu, sacc, off);
        if (l == 0) out[bbase + b] = sacc + b_out[0];
    }
}

extern "C" void kernel_launch(void* const* d_in, const int* in_sizes, int n_in,
                              void* d_out, int out_size) {
    const float* xs    = (const float*)d_in[0];
    const float* W_ih  = (const float*)d_in[1];
    const float* W_hh  = (const float*)d_in[2];
    const float* b_ih  = (const float*)d_in[3];
    const float* b_hh  = (const float*)d_in[4];
    const float* W_out = (const float*)d_in[5];
    const float* b_out = (const float*)d_in[6];

    rnn_fused_kernel<<<NBLK, NTHR>>>(xs, W_ih, W_hh, b_ih, b_hh, W_out, b_out,
                                     (float*)d_out);
}

// round 12
// speedup vs baseline: 1.4918x; 1.4918x over previous
#include <cuda_runtime.h>
#include <cuda_bf16.h>
#include <cstdint>

#define SEQ    2048
#define BATCH  512
#define INPT   64
#define HIDDEN 128
#define KTOT   192
#define BB     4
#define NBLK   (BATCH / BB)    // 128 blocks, 1/SM
#define NTHR   256             // 8 warps, warp w owns j rows [16w, 16w+16)
#define NKT    (KTOT / 16)     // 12 k-tiles

__device__ __forceinline__ float tanh_fast(float z) {
    float az = fabsf(z);
    float e  = __expf(-2.0f * az);
    float r  = __fdividef(1.0f - e, 1.0f + e);
    return copysignf(r, z);
}
__device__ __forceinline__ void cp16(void* smem_dst, const float* gsrc) {
    unsigned dst = (unsigned)__cvta_generic_to_shared(smem_dst);
    asm volatile("cp.async.ca.shared.global [%0], [%1], 16;" :: "r"(dst), "l"(gsrc));
}
__device__ __forceinline__ float wcomb(const float* W_ih, const float* W_hh,
                                       int j, int c) {
    return (c < INPT) ? W_ih[j * INPT + c] : W_hh[j * HIDDEN + (c - INPT)];
}
__device__ __forceinline__ void split_bf(float v, __nv_bfloat16& hi,
                                         __nv_bfloat16& lo) {
    hi = __float2bfloat16(v);
    lo = __float2bfloat16(v - __bfloat162float(hi));
}
__device__ __forceinline__ uint32_t pack2bf(__nv_bfloat16 a, __nv_bfloat16 b) {
    __nv_bfloat162 t(a, b);                 // a -> low 16 bits
    return *reinterpret_cast<uint32_t*>(&t);
}
// D += A(16x16 bf16, row) @ B(16x8 bf16, col), fp32 accum, in place
__device__ __forceinline__ void mma16816(float* d, const uint32_t* a,
                                         uint32_t b0, uint32_t b1) {
    asm volatile(
        "mma.sync.aligned.m16n8k16.row.col.f32.bf16.bf16.f32 "
        "{%0,%1,%2,%3}, {%4,%5,%6,%7}, {%8,%9}, {%0,%1,%2,%3};"
        : "+f"(d[0]), "+f"(d[1]), "+f"(d[2]), "+f"(d[3])
        : "r"(a[0]), "r"(a[1]), "r"(a[2]), "r"(a[3]), "r"(b0), "r"(b1));
}

// u layout: uint32 word (kp, n) = bf16 pair {k=2kp, k=2kp+1} of batch n;
// index = kp*8 + n, kp in [0,96), n in [0,8) (n>=4 stay zero).
__global__ void __launch_bounds__(NTHR, 1)
rnn_hmma_kernel(const float* __restrict__ xs,
                const float* __restrict__ W_ih,
                const float* __restrict__ W_hh,
                const float* __restrict__ b_ih,
                const float* __restrict__ b_hh,
                const float* __restrict__ W_out,
                const float* __restrict__ b_out,
                float* __restrict__ out) {
    __shared__ uint32_t uHi[2][96 * 8];
    __shared__ uint32_t uLo[2][96 * 8];
    __shared__ __align__(16) float stage[3][BB][INPT];
    __shared__ float red[BB][HIDDEN];

    const int tid  = threadIdx.x;
    const int wid  = tid >> 5;
    const int lane = tid & 31;
    const int g    = lane >> 2;           // fragment row
    const int q    = lane & 3;            // fragment col pair
    const long bbase = (long)blockIdx.x * BB;

    const int j0 = 16 * wid + g;
    const int j1 = j0 + 8;
    const bool act = (q < 2);             // lanes owning valid batches
    const int b0n = 2 * q;                // batch of d0/d2 (valid iff act)

    // ---- A fragments (weights) in registers: 12 kt x {hi,lo} x 4 regs ----
    uint32_t aH[NKT][4], aL[NKT][4];
    #pragma unroll
    for (int kt = 0; kt < NKT; kt++) {
        int c0 = kt * 16 + 2 * q;
        float w00 = wcomb(W_ih, W_hh, j0, c0);
        float w01 = wcomb(W_ih, W_hh, j0, c0 + 1);
        float w10 = wcomb(W_ih, W_hh, j1, c0);
        float w11 = wcomb(W_ih, W_hh, j1, c0 + 1);
        float w02 = wcomb(W_ih, W_hh, j0, c0 + 8);
        float w03 = wcomb(W_ih, W_hh, j0, c0 + 9);
        float w12 = wcomb(W_ih, W_hh, j1, c0 + 8);
        float w13 = wcomb(W_ih, W_hh, j1, c0 + 9);
        __nv_bfloat16 h, l, h2, l2;
        split_bf(w00, h, l); split_bf(w01, h2, l2);
        aH[kt][0] = pack2bf(h, h2); aL[kt][0] = pack2bf(l, l2);
        split_bf(w10, h, l); split_bf(w11, h2, l2);
        aH[kt][1] = pack2bf(h, h2); aL[kt][1] = pack2bf(l, l2);
        split_bf(w02, h, l); split_bf(w03, h2, l2);
        aH[kt][2] = pack2bf(h, h2); aL[kt][2] = pack2bf(l, l2);
        split_bf(w12, h, l); split_bf(w13, h2, l2);
        aH[kt][3] = pack2bf(h, h2); aL[kt][3] = pack2bf(l, l2);
    }
    const float bias0 = b_ih[j0] + b_hh[j0];
    const float bias1 = b_ih[j1] + b_hh[j1];

    // h-store base index (bf16 units) for (j0, b0n): k = 64 + j -> kp = 32+j/2
    const int hidx = ((32 + (j0 >> 1)) * 8 + b0n) * 2 + (j0 & 1);

    // ---- init: zero u, write x(0), stage x(1), x(2) ----
    for (int i = tid; i < 2 * 96 * 8; i += NTHR) {
        (&uHi[0][0])[i] = 0u;
        (&uLo[0][0])[i] = 0u;
    }
    __syncthreads();
    if (tid < 128) {
        int b = tid & 3, kp = tid >> 2;    // kp in [0,32): x region
        const float* xp = xs + (bbase + b) * INPT + 2 * kp;
        __nv_bfloat16 h0, l0, h1, l1;
        split_bf(xp[0], h0, l0); split_bf(xp[1], h1, l1);
        uHi[0][kp * 8 + b] = pack2bf(h0, h1);
        uLo[0][kp * 8 + b] = pack2bf(l0, l1);
    }
    if (tid < 64) {
        int b = tid >> 4, seg = tid & 15;
        cp16(&stage[1][b][seg * 4],
             xs + ((long)1 * BATCH + bbase + b) * INPT + seg * 4);
    }
    asm volatile("cp.async.commit_group;" ::);
    if (tid < 64) {
        int b = tid >> 4, seg = tid & 15;
        cp16(&stage[2][b][seg * 4],
             xs + ((long)2 * BATCH + bbase + b) * INPT + seg * 4);
    }
    asm volatile("cp.async.commit_group;" ::);
    __syncthreads();

    __nv_bfloat16* phN; __nv_bfloat16* plN;   // set per step

    for (int t = 0; t < SEQ - 1; ++t) {
        const int cur = t & 1, nxt = cur ^ 1;

        // prefetch x(t+3) -> stage[t%3]
        if (t + 3 < SEQ && tid < 64) {
            int b = tid >> 4, seg = tid & 15;
            cp16(&stage[t % 3][b][seg * 4],
                 xs + ((long)(t + 3) * BATCH + bbase + b) * INPT + seg * 4);
        }
        asm volatile("cp.async.commit_group;" ::);
        asm volatile("cp.async.wait_group 2;" ::);

        // convert x(t+1) -> u[nxt] x-region
        if (tid < 128) {
            int b = tid & 3, kp = tid >> 2;
            const float* sp = &stage[(t + 1) % 3][b][2 * kp];
            __nv_bfloat16 h0, l0, h1, l1;
            split_bf(sp[0], h0, l0); split_bf(sp[1], h1, l1);
            uHi[nxt][kp * 8 + b] = pack2bf(h0, h1);
            uLo[nxt][kp * 8 + b] = pack2bf(l0, l1);
        }

        // ---- 36 HMMA: three independent accumulator chains ----
        float D1[4] = {0, 0, 0, 0}, D2[4] = {0, 0, 0, 0}, D3[4] = {0, 0, 0, 0};
        #pragma unroll
        for (int kt = 0; kt < NKT; kt++) {
            int wi = (kt * 8 + q) * 8 + g;
            uint32_t bh0 = uHi[cur][wi], bh1 = uHi[cur][wi + 32];
            uint32_t bl0 = uLo[cur][wi], bl1 = uLo[cur][wi + 32];
            mma16816(D1, aH[kt], bh0, bh1);
            mma16816(D2, aL[kt], bh0, bh1);
            mma16816(D3, aH[kt], bl0, bl1);
        }

        // ---- epilogue: h(t+1) for this lane's 4 (j,b) slots ----
        if (act) {
            float h00 = tanh_fast(D1[0] + D2[0] + D3[0] + bias0);
            float h01 = tanh_fast(D1[1] + D2[1] + D3[1] + bias0);
            float h10 = tanh_fast(D1[2] + D2[2] + D3[2] + bias1);
            float h11 = tanh_fast(D1[3] + D2[3] + D3[3] + bias1);
            phN = reinterpret_cast<__nv_bfloat16*>(&uHi[nxt][0]);
            plN = reinterpret_cast<__nv_bfloat16*>(&uLo[nxt][0]);
            __nv_bfloat16 hh, ll;
            split_bf(h00, hh, ll); phN[hidx]      = hh; plN[hidx]      = ll;
            split_bf(h01, hh, ll); phN[hidx + 2]  = hh; plN[hidx + 2]  = ll;
            split_bf(h10, hh, ll); phN[hidx + 64] = hh; plN[hidx + 64] = ll;
            split_bf(h11, hh, ll); phN[hidx + 66] = hh; plN[hidx + 66] = ll;
        }
        __syncthreads();
    }

    // ---- peeled final step (t = SEQ-1, cur = 1): h_final -> red (fp32) ----
    {
        const int cur = (SEQ - 1) & 1;
        float D1[4] = {0, 0, 0, 0}, D2[4] = {0, 0, 0, 0}, D3[4] = {0, 0, 0, 0};
        #pragma unroll
        for (int kt = 0; kt < NKT; kt++) {
            int wi = (kt * 8 + q) * 8 + g;
            uint32_t bh0 = uHi[cur][wi], bh1 = uHi[cur][wi + 32];
            uint32_t bl0 = uLo[cur][wi], bl1 = uLo[cur][wi + 32];
            mma16816(D1, aH[kt], bh0, bh1);
            mma16816(D2, aL[kt], bh0, bh1);
            mma16816(D3, aH[kt], bl0, bl1);
        }
        if (act) {
            red[b0n][j0]     = tanh_fast(D1[0] + D2[0] + D3[0] + bias0);
            red[b0n + 1][j0] = tanh_fast(D1[1] + D2[1] + D3[1] + bias0);
            red[b0n][j1]     = tanh_fast(D1[2] + D2[2] + D3[2] + bias1);
            red[b0n + 1][j1] = tanh_fast(D1[3] + D2[3] + D3[3] + bias1);
        }
        __syncthreads();
    }

    // ---- output projection: out[b] = h_final[b] . W_out + b_out ----
    if (wid < BB) {
        int b = wid;
        float s = 0.0f;
        #pragma unroll
        for (int m = 0; m < 4; m++) {
            int jj = lane + 32 * m;
            s += red[b][jj] * W_out[jj];
        }
        #pragma unroll
        for (int off = 16; off; off >>= 1)
            s += __shfl_down_sync(0xffffffffu, s, off);
        if (lane == 0) out[bbase + b] = s + b_out[0];
    }
}

extern "C" void kernel_launch(void* const* d_in, const int* in_sizes, int n_in,
                              void* d_out, int out_size) {
    const float* xs    = (const float*)d_in[0];
    const float* W_ih  = (const float*)d_in[1];
    const float* W_hh  = (const float*)d_in[2];
    const float* b_ih  = (const float*)d_in[3];
    const float* b_hh  = (const float*)d_in[4];
    const float* W_out = (const float*)d_in[5];
    const float* b_out = (const float*)d_in[6];

    rnn_hmma_kernel<<<NBLK, NTHR>>>(xs, W_ih, W_hh, b_ih, b_hh, W_out, b_out,
                                    (float*)d_out);
}